// round 5
// baseline (speedup 1.0000x reference)
#include <cuda_runtime.h>

// SigNet: depth-4 path signature (C=8 incl. time) + linear head.
// K1: 8-way segmented scalar Chen scan (factored updates) + in-smem tree combine.
//     T[8][4680] overlaps the increment table (scan reads finish first).
// K2: split-k GEMM (KSPLIT=21).  K3: reduce + bias.

#define NB      128
#define SLEN    1024
#define NSEG    8
#define SEG     128
#define CIN     7
#define SIGCH   4680          // 8 + 64 + 512 + 4096
#define YSTRIDE 4704
#define DOUT    256
#define KSPLIT  21
#define KCHUNK  224           // 21*224 = 4704

__device__ float g_y[NB * YSTRIDE];
__device__ float g_part[KSPLIT * NB * DOUT];

// smem: vs[1024][8] = 8192 floats, then reused as T[8][4680] = 37440 floats.
#define SMEM_FLOATS (NSEG * SIGCH)     // 37440 floats = 149760 B

// ---- Chen combine pieces (X = A o B, A earlier in time) ----
__device__ __forceinline__ void chen_l4(const float* __restrict__ A,
                                        const float* __restrict__ B,
                                        float* __restrict__ X, int lane, int nth)
{
    for (int e = lane; e < 4096; e += nth) {
        float v = A[584 + e] + B[584 + e];
        v = fmaf(A[e >> 9],        B[72 + (e & 511)], v);
        v = fmaf(A[8 + (e >> 6)],  B[8  + (e & 63)],  v);
        v = fmaf(A[72 + (e >> 3)], B[e & 7],          v);
        X[584 + e] = v;
    }
}
__device__ __forceinline__ void chen_l3(const float* __restrict__ A,
                                        const float* __restrict__ B,
                                        float* __restrict__ X, int lane, int nth)
{
    for (int e = lane; e < 512; e += nth) {
        float v = A[72 + e] + B[72 + e];
        v = fmaf(A[e >> 6],       B[8 + (e & 63)], v);
        v = fmaf(A[8 + (e >> 3)], B[e & 7],        v);
        X[72 + e] = v;
    }
}

// In-place combine: A <- A o B. nth threads, lane in [0,nth).
// Internal syncs are CTA-wide; every thread of the CTA runs the same sequence.
__device__ __forceinline__ void chen_inplace(float* __restrict__ A,
                                             const float* __restrict__ B,
                                             int lane, int nth)
{
    chen_l4(A, B, A, lane, nth);      // reads A[0..584), writes A[584..)
    __syncthreads();
    chen_l3(A, B, A, lane, nth);      // reads A[0..72), writes A[72..584)
    float v2 = 0.0f, v1 = 0.0f;
    if (lane < 64) v2 = A[8 + lane] + B[8 + lane] + A[lane >> 3] * B[lane & 7];
    if (lane < 8)  v1 = A[lane] + B[lane];
    __syncthreads();
    if (lane < 64) A[8 + lane] = v2;
    if (lane < 8)  A[lane] = v1;
}

// ---------------------------------------------------------------------------
// Kernel 1: segmented scan. 1 CTA/batch, 512 threads = 8 groups x 64.
// Thread u=tid&63 owns (a,b)=(u>>3,u&7): all 8 c, all 8 d (64 L4 accumulators).
// ---------------------------------------------------------------------------
__global__ __launch_bounds__(512, 1) void sig_scan_kernel(const float* __restrict__ inp)
{
    extern __shared__ float sm[];
    const int b   = blockIdx.x;
    const int tid = threadIdx.x;

    // Build increments into sm[0..8192). Basepoint 0: first inc = first sample.
    const float dt = 1.0f / 1023.0f;
    const float* x = inp + (size_t)b * SLEN * CIN;
    for (int i = tid; i < SLEN * CIN; i += 512) {
        int t = i / CIN, c = i - t * CIN;
        float cur  = x[i];
        float prev = (t == 0) ? 0.0f : x[i - CIN];
        sm[t * 8 + c + 1] = cur - prev;
    }
    for (int t = tid; t < SLEN; t += 512)
        sm[t * 8] = (t == 0) ? 0.0f : dt;
    __syncthreads();

    const int g  = tid >> 6;          // segment 0..7
    const int u  = tid & 63;          // (a,b)
    const int a  = u >> 3;
    const int bb = u & 7;

    float s1 = 0.0f, s2 = 0.0f;
    float s3[8];
    float sig4[64];
#pragma unroll
    for (int i = 0; i < 8; i++) s3[i] = 0.0f;
#pragma unroll
    for (int i = 0; i < 64; i++) sig4[i] = 0.0f;

    const float inv24 = 1.0f / 24.0f;
    const float inv6  = 1.0f / 6.0f;
    const float* vrow = sm + g * SEG * 8;

#pragma unroll 1
    for (int t = 0; t < SEG; t++) {
        float vv[8];
        *(float4*)&vv[0] = *(const float4*)&vrow[t * 8];
        *(float4*)&vv[4] = *(const float4*)&vrow[t * 8 + 4];
        float va = vv[a];
        float vb = vv[bb];

        // All derived from OLD s1,s2,s3.
        float t6 = fmaf(s1, inv6, va * inv24);   // va/24 + s1/6
        float uu = fmaf(s1, 0.5f, va * inv6);    // va/6  + s1/2
        float m1 = fmaf(vb, t6, s2 * 0.5f);      // vb*t6 + s2/2
        float m2 = fmaf(vb, uu, s2);             // vb*uu + s2

        float K[8];
#pragma unroll
        for (int c = 0; c < 8; c++) {
            K[c]  = fmaf(vv[c], m1, s3[c]);
            s3[c] = fmaf(vv[c], m2, s3[c]);
        }
#pragma unroll
        for (int c = 0; c < 8; c++)
#pragma unroll
            for (int d = 0; d < 8; d++)
                sig4[c * 8 + d] = fmaf(K[c], vv[d], sig4[c * 8 + d]);

        s2 = fmaf(vb, fmaf(va, 0.5f, s1), s2);   // s2 + va*vb/2 + s1*vb
        s1 += va;
    }

    // All scan reads of sm done -> safe to overwrite with T[8][4680].
    __syncthreads();

    float* P = sm + g * SIGCH;
#pragma unroll 1
    for (int c = 0; c < 8; c++) {
#pragma unroll
        for (int d = 0; d < 8; d++)
            P[584 + u * 64 + c * 8 + d] = sig4[c * 8 + d];
        P[72 + u * 8 + c] = s3[c];
    }
    P[8 + u] = s2;
    if (bb == 0) P[a] = s1;
    __syncthreads();

    // Round 1: 4 parallel in-place combines, 128 threads each.
    {
        int pair = tid >> 7, lane = tid & 127;
        float* A = sm + (2 * pair) * SIGCH;
        const float* B = A + SIGCH;
        chen_inplace(A, B, lane, 128);
    }
    __syncthreads();
    // Round 2: 2 parallel in-place combines, 256 threads each.
    {
        int pair = tid >> 8, lane = tid & 255;
        float* A = sm + (4 * pair) * SIGCH;
        const float* B = A + 2 * SIGCH;
        chen_inplace(A, B, lane, 256);
    }
    __syncthreads();
    // Round 3: final combine straight to global.
    {
        const float* A = sm;
        const float* B = sm + 4 * SIGCH;
        float* y = g_y + (size_t)b * YSTRIDE;
        chen_l4(A, B, y, tid, 512);
        chen_l3(A, B, y, tid, 512);
        if (tid < 64) y[8 + tid] = A[8 + tid] + B[8 + tid] + A[tid >> 3] * B[tid & 7];
        if (tid < 8)  y[tid] = A[tid] + B[tid];
        if (tid < YSTRIDE - SIGCH) y[SIGCH + tid] = 0.0f;
    }
}

// ---------------------------------------------------------------------------
// Kernel 2: split-k GEMM partials. grid = (16 col-groups, KSPLIT).
// CTA: 128 batch-rows x 16 out-cols over KCHUNK of k. 256 threads.
// ---------------------------------------------------------------------------
__global__ __launch_bounds__(256, 1) void gemm_part_kernel(const float* __restrict__ W)
{
    __shared__ float ys[128][32];
    __shared__ float ws[16][33];

    const int tid = threadIdx.x;
    const int cg = blockIdx.x;
    const int sp = blockIdx.y;
    const int kbase = sp * KCHUNK;

    const int cp = tid & 7;        // col pair: cols 2cp, 2cp+1
    const int rg = tid >> 3;       // rows rg + 32*j

    float acc00 = 0.f, acc01 = 0.f, acc02 = 0.f, acc03 = 0.f;
    float acc10 = 0.f, acc11 = 0.f, acc12 = 0.f, acc13 = 0.f;

    for (int kc = 0; kc < KCHUNK; kc += 32) {
        const int k0 = kbase + kc;
#pragma unroll
        for (int ii = 0; ii < 4; ii++) {
            int lin = tid + 256 * ii;
            int r = lin >> 3, seg = lin & 7;
            float4 val = *(const float4*)&g_y[r * YSTRIDE + k0 + seg * 4];
            *(float4*)&ys[r][seg * 4] = val;
        }
#pragma unroll
        for (int ii = 0; ii < 2; ii++) {
            int lin = tid + 256 * ii;
            int r = lin >> 5, cc = lin & 31;
            int k = k0 + cc;
            ws[r][cc] = (k < SIGCH) ? W[(cg * 16 + r) * SIGCH + k] : 0.0f;
        }
        __syncthreads();
#pragma unroll
        for (int kk = 0; kk < 32; kk += 2) {
            float2 w0 = *(const float2*)&ws[2 * cp][kk];
            float2 w1 = *(const float2*)&ws[2 * cp + 1][kk];
            float2 y0 = *(const float2*)&ys[rg][kk];
            float2 y1 = *(const float2*)&ys[rg + 32][kk];
            float2 y2 = *(const float2*)&ys[rg + 64][kk];
            float2 y3 = *(const float2*)&ys[rg + 96][kk];
            acc00 = fmaf(y0.x, w0.x, acc00); acc00 = fmaf(y0.y, w0.y, acc00);
            acc01 = fmaf(y1.x, w0.x, acc01); acc01 = fmaf(y1.y, w0.y, acc01);
            acc02 = fmaf(y2.x, w0.x, acc02); acc02 = fmaf(y2.y, w0.y, acc02);
            acc03 = fmaf(y3.x, w0.x, acc03); acc03 = fmaf(y3.y, w0.y, acc03);
            acc10 = fmaf(y0.x, w1.x, acc10); acc10 = fmaf(y0.y, w1.y, acc10);
            acc11 = fmaf(y1.x, w1.x, acc11); acc11 = fmaf(y1.y, w1.y, acc11);
            acc12 = fmaf(y2.x, w1.x, acc12); acc12 = fmaf(y2.y, w1.y, acc12);
            acc13 = fmaf(y3.x, w1.x, acc13); acc13 = fmaf(y3.y, w1.y, acc13);
        }
        __syncthreads();
    }

    const int col0 = cg * 16 + 2 * cp;
    float* p = g_part + (size_t)sp * NB * DOUT;
    p[(rg +  0) * DOUT + col0]     = acc00;
    p[(rg + 32) * DOUT + col0]     = acc01;
    p[(rg + 64) * DOUT + col0]     = acc02;
    p[(rg + 96) * DOUT + col0]     = acc03;
    p[(rg +  0) * DOUT + col0 + 1] = acc10;
    p[(rg + 32) * DOUT + col0 + 1] = acc11;
    p[(rg + 64) * DOUT + col0 + 1] = acc12;
    p[(rg + 96) * DOUT + col0 + 1] = acc13;
}

// ---------------------------------------------------------------------------
__global__ void reduce_bias_kernel(const float* __restrict__ bias, float* __restrict__ out)
{
    int idx = blockIdx.x * 256 + threadIdx.x;
    float v = bias[idx & (DOUT - 1)];
#pragma unroll
    for (int s = 0; s < KSPLIT; s++)
        v += g_part[s * NB * DOUT + idx];
    out[idx] = v;
}

// ---------------------------------------------------------------------------
extern "C" void kernel_launch(void* const* d_in, const int* in_sizes, int n_in,
                              void* d_out, int out_size)
{
    (void)in_sizes; (void)n_in; (void)out_size;
    const float* inp  = (const float*)d_in[0];   // (128,1024,7)
    const float* W    = (const float*)d_in[1];   // (256,4680)
    const float* bias = (const float*)d_in[2];   // (256,)
    float* out = (float*)d_out;                  // (128,256)

    const int smem_bytes = SMEM_FLOATS * sizeof(float);   // 149760
    cudaFuncSetAttribute(sig_scan_kernel,
                         cudaFuncAttributeMaxDynamicSharedMemorySize, smem_bytes);

    sig_scan_kernel<<<NB, 512, smem_bytes>>>(inp);
    dim3 g2(16, KSPLIT);
    gemm_part_kernel<<<g2, 256>>>(W);
    reduce_bias_kernel<<<NB, 256>>>(bias, out);
}

// round 6
// speedup vs baseline: 1.4191x; 1.4191x over previous
#include <cuda_runtime.h>

// SigNet: depth-4 path signature (C=8 incl. time) + linear head.
// K1: 8-way segmented scalar Chen scan (factored updates) + in-smem tree combine.
//     T[8][4680] overlaps the increment table (scan reads finish first).
//     NOTE: no dynamic indexing of register arrays anywhere (vv[a] / sig4[c*8+d]
//     with runtime c forced local-memory spills in R5 -- L2=37.6% signature).
// K2: split-k GEMM (KSPLIT=21).  K3: reduce + bias.

#define NB      128
#define SLEN    1024
#define NSEG    8
#define SEG     128
#define CIN     7
#define SIGCH   4680          // 8 + 64 + 512 + 4096
#define YSTRIDE 4704
#define DOUT    256
#define KSPLIT  21
#define KCHUNK  224           // 21*224 = 4704

__device__ float g_y[NB * YSTRIDE];
__device__ float g_part[KSPLIT * NB * DOUT];

// smem: vs[1024][8] = 8192 floats, then reused as T[8][4680] = 37440 floats.
#define SMEM_FLOATS (NSEG * SIGCH)     // 37440 floats = 149760 B

// ---- Chen combine pieces (X = A o B, A earlier in time) ----
__device__ __forceinline__ void chen_l4(const float* __restrict__ A,
                                        const float* __restrict__ B,
                                        float* __restrict__ X, int lane, int nth)
{
    for (int e = lane; e < 4096; e += nth) {
        float v = A[584 + e] + B[584 + e];
        v = fmaf(A[e >> 9],        B[72 + (e & 511)], v);
        v = fmaf(A[8 + (e >> 6)],  B[8  + (e & 63)],  v);
        v = fmaf(A[72 + (e >> 3)], B[e & 7],          v);
        X[584 + e] = v;
    }
}
__device__ __forceinline__ void chen_l3(const float* __restrict__ A,
                                        const float* __restrict__ B,
                                        float* __restrict__ X, int lane, int nth)
{
    for (int e = lane; e < 512; e += nth) {
        float v = A[72 + e] + B[72 + e];
        v = fmaf(A[e >> 6],       B[8 + (e & 63)], v);
        v = fmaf(A[8 + (e >> 3)], B[e & 7],        v);
        X[72 + e] = v;
    }
}

// In-place combine: A <- A o B. nth threads, lane in [0,nth).
// Internal syncs are CTA-wide; every thread of the CTA runs the same sequence.
__device__ __forceinline__ void chen_inplace(float* __restrict__ A,
                                             const float* __restrict__ B,
                                             int lane, int nth)
{
    chen_l4(A, B, A, lane, nth);      // reads A[0..584), writes A[584..)
    __syncthreads();
    chen_l3(A, B, A, lane, nth);      // reads A[0..72), writes A[72..584)
    float v2 = 0.0f, v1 = 0.0f;
    if (lane < 64) v2 = A[8 + lane] + B[8 + lane] + A[lane >> 3] * B[lane & 7];
    if (lane < 8)  v1 = A[lane] + B[lane];
    __syncthreads();
    if (lane < 64) A[8 + lane] = v2;
    if (lane < 8)  A[lane] = v1;
}

// ---------------------------------------------------------------------------
// Kernel 1: segmented scan. 1 CTA/batch, 512 threads = 8 groups x 64.
// Thread u=tid&63 owns (a,b)=(u>>3,u&7): all 8 c, all 8 d (64 L4 accumulators).
// ---------------------------------------------------------------------------
__global__ __launch_bounds__(512, 1) void sig_scan_kernel(const float* __restrict__ inp)
{
    extern __shared__ float sm[];
    const int b   = blockIdx.x;
    const int tid = threadIdx.x;

    // Build increments into sm[0..8192). Basepoint 0: first inc = first sample.
    const float dt = 1.0f / 1023.0f;
    const float* x = inp + (size_t)b * SLEN * CIN;
    for (int i = tid; i < SLEN * CIN; i += 512) {
        int t = i / CIN, c = i - t * CIN;
        float cur  = x[i];
        float prev = (t == 0) ? 0.0f : x[i - CIN];
        sm[t * 8 + c + 1] = cur - prev;
    }
    for (int t = tid; t < SLEN; t += 512)
        sm[t * 8] = (t == 0) ? 0.0f : dt;
    __syncthreads();

    const int g  = tid >> 6;          // segment 0..7
    const int u  = tid & 63;          // (a,b)
    const int a  = u >> 3;
    const int bb = u & 7;

    float s1 = 0.0f, s2 = 0.0f;
    float s3[8];
    float sig4[64];
#pragma unroll
    for (int i = 0; i < 8; i++) s3[i] = 0.0f;
#pragma unroll
    for (int i = 0; i < 64; i++) sig4[i] = 0.0f;

    const float inv24 = 1.0f / 24.0f;
    const float inv6  = 1.0f / 6.0f;
    const float* vrow = sm + g * SEG * 8;

#pragma unroll 1
    for (int t = 0; t < SEG; t++) {
        float vv[8];
        *(float4*)&vv[0] = *(const float4*)&vrow[t * 8];
        *(float4*)&vv[4] = *(const float4*)&vrow[t * 8 + 4];
        // Runtime-offset reads come from SHARED (LDS), never from the register
        // array: vv[a] would force vv into local memory.
        float va = vrow[t * 8 + a];
        float vb = vrow[t * 8 + bb];

        // All derived from OLD s1,s2,s3.
        float t6 = fmaf(s1, inv6, va * inv24);   // va/24 + s1/6
        float uu = fmaf(s1, 0.5f, va * inv6);    // va/6  + s1/2
        float m1 = fmaf(vb, t6, s2 * 0.5f);      // vb*t6 + s2/2
        float m2 = fmaf(vb, uu, s2);             // vb*uu + s2

        float K[8];
#pragma unroll
        for (int c = 0; c < 8; c++) {
            K[c]  = fmaf(vv[c], m1, s3[c]);
            s3[c] = fmaf(vv[c], m2, s3[c]);
        }
#pragma unroll
        for (int c = 0; c < 8; c++)
#pragma unroll
            for (int d = 0; d < 8; d++)
                sig4[c * 8 + d] = fmaf(K[c], vv[d], sig4[c * 8 + d]);

        s2 = fmaf(vb, fmaf(va, 0.5f, s1), s2);   // s2 + va*vb/2 + s1*vb
        s1 += va;
    }

    // All scan reads of sm done -> safe to overwrite with T[8][4680].
    __syncthreads();

    // Fully unrolled write-out: every sig4 index is a compile-time constant.
    float* P = sm + g * SIGCH;
#pragma unroll
    for (int c = 0; c < 8; c++) {
#pragma unroll
        for (int d = 0; d < 8; d++)
            P[584 + u * 64 + c * 8 + d] = sig4[c * 8 + d];
        P[72 + u * 8 + c] = s3[c];
    }
    P[8 + u] = s2;
    if (bb == 0) P[a] = s1;
    __syncthreads();

    // Round 1: 4 parallel in-place combines, 128 threads each.
    {
        int pair = tid >> 7, lane = tid & 127;
        float* A = sm + (2 * pair) * SIGCH;
        const float* B = A + SIGCH;
        chen_inplace(A, B, lane, 128);
    }
    __syncthreads();
    // Round 2: 2 parallel in-place combines, 256 threads each.
    {
        int pair = tid >> 8, lane = tid & 255;
        float* A = sm + (4 * pair) * SIGCH;
        const float* B = A + 2 * SIGCH;
        chen_inplace(A, B, lane, 256);
    }
    __syncthreads();
    // Round 3: final combine straight to global.
    {
        const float* A = sm;
        const float* B = sm + 4 * SIGCH;
        float* y = g_y + (size_t)b * YSTRIDE;
        chen_l4(A, B, y, tid, 512);
        chen_l3(A, B, y, tid, 512);
        if (tid < 64) y[8 + tid] = A[8 + tid] + B[8 + tid] + A[tid >> 3] * B[tid & 7];
        if (tid < 8)  y[tid] = A[tid] + B[tid];
        if (tid < YSTRIDE - SIGCH) y[SIGCH + tid] = 0.0f;
    }
}

// ---------------------------------------------------------------------------
// Kernel 2: split-k GEMM partials. grid = (16 col-groups, KSPLIT).
// CTA: 128 batch-rows x 16 out-cols over KCHUNK of k. 256 threads.
// ---------------------------------------------------------------------------
__global__ __launch_bounds__(256, 1) void gemm_part_kernel(const float* __restrict__ W)
{
    __shared__ float ys[128][32];
    __shared__ float ws[16][33];

    const int tid = threadIdx.x;
    const int cg = blockIdx.x;
    const int sp = blockIdx.y;
    const int kbase = sp * KCHUNK;

    const int cp = tid & 7;        // col pair: cols 2cp, 2cp+1
    const int rg = tid >> 3;       // rows rg + 32*j

    float acc00 = 0.f, acc01 = 0.f, acc02 = 0.f, acc03 = 0.f;
    float acc10 = 0.f, acc11 = 0.f, acc12 = 0.f, acc13 = 0.f;

    for (int kc = 0; kc < KCHUNK; kc += 32) {
        const int k0 = kbase + kc;
#pragma unroll
        for (int ii = 0; ii < 4; ii++) {
            int lin = tid + 256 * ii;
            int r = lin >> 3, seg = lin & 7;
            float4 val = *(const float4*)&g_y[r * YSTRIDE + k0 + seg * 4];
            *(float4*)&ys[r][seg * 4] = val;
        }
#pragma unroll
        for (int ii = 0; ii < 2; ii++) {
            int lin = tid + 256 * ii;
            int r = lin >> 5, cc = lin & 31;
            int k = k0 + cc;
            ws[r][cc] = (k < SIGCH) ? W[(cg * 16 + r) * SIGCH + k] : 0.0f;
        }
        __syncthreads();
#pragma unroll
        for (int kk = 0; kk < 32; kk += 2) {
            float2 w0 = *(const float2*)&ws[2 * cp][kk];
            float2 w1 = *(const float2*)&ws[2 * cp + 1][kk];
            float2 y0 = *(const float2*)&ys[rg][kk];
            float2 y1 = *(const float2*)&ys[rg + 32][kk];
            float2 y2 = *(const float2*)&ys[rg + 64][kk];
            float2 y3 = *(const float2*)&ys[rg + 96][kk];
            acc00 = fmaf(y0.x, w0.x, acc00); acc00 = fmaf(y0.y, w0.y, acc00);
            acc01 = fmaf(y1.x, w0.x, acc01); acc01 = fmaf(y1.y, w0.y, acc01);
            acc02 = fmaf(y2.x, w0.x, acc02); acc02 = fmaf(y2.y, w0.y, acc02);
            acc03 = fmaf(y3.x, w0.x, acc03); acc03 = fmaf(y3.y, w0.y, acc03);
            acc10 = fmaf(y0.x, w1.x, acc10); acc10 = fmaf(y0.y, w1.y, acc10);
            acc11 = fmaf(y1.x, w1.x, acc11); acc11 = fmaf(y1.y, w1.y, acc11);
            acc12 = fmaf(y2.x, w1.x, acc12); acc12 = fmaf(y2.y, w1.y, acc12);
            acc13 = fmaf(y3.x, w1.x, acc13); acc13 = fmaf(y3.y, w1.y, acc13);
        }
        __syncthreads();
    }

    const int col0 = cg * 16 + 2 * cp;
    float* p = g_part + (size_t)sp * NB * DOUT;
    p[(rg +  0) * DOUT + col0]     = acc00;
    p[(rg + 32) * DOUT + col0]     = acc01;
    p[(rg + 64) * DOUT + col0]     = acc02;
    p[(rg + 96) * DOUT + col0]     = acc03;
    p[(rg +  0) * DOUT + col0 + 1] = acc10;
    p[(rg + 32) * DOUT + col0 + 1] = acc11;
    p[(rg + 64) * DOUT + col0 + 1] = acc12;
    p[(rg + 96) * DOUT + col0 + 1] = acc13;
}

// ---------------------------------------------------------------------------
__global__ void reduce_bias_kernel(const float* __restrict__ bias, float* __restrict__ out)
{
    int idx = blockIdx.x * 256 + threadIdx.x;
    float v = bias[idx & (DOUT - 1)];
#pragma unroll
    for (int s = 0; s < KSPLIT; s++)
        v += g_part[s * NB * DOUT + idx];
    out[idx] = v;
}

// ---------------------------------------------------------------------------
extern "C" void kernel_launch(void* const* d_in, const int* in_sizes, int n_in,
                              void* d_out, int out_size)
{
    (void)in_sizes; (void)n_in; (void)out_size;
    const float* inp  = (const float*)d_in[0];   // (128,1024,7)
    const float* W    = (const float*)d_in[1];   // (256,4680)
    const float* bias = (const float*)d_in[2];   // (256,)
    float* out = (float*)d_out;                  // (128,256)

    const int smem_bytes = SMEM_FLOATS * sizeof(float);   // 149760
    cudaFuncSetAttribute(sig_scan_kernel,
                         cudaFuncAttributeMaxDynamicSharedMemorySize, smem_bytes);

    sig_scan_kernel<<<NB, 512, smem_bytes>>>(inp);
    dim3 g2(16, KSPLIT);
    gemm_part_kernel<<<g2, 256>>>(W);
    reduce_bias_kernel<<<NB, 256>>>(bias, out);
}